// round 1
// baseline (speedup 1.0000x reference)
#include <cuda_runtime.h>
#include <cuda_bf16.h>

#define NF   100000
#define CLIP 50
#define D    64

__global__ __launch_bounds__(256, 8)
void gmf_kernel(const int*   __restrict__ user_indices,
                const int*   __restrict__ item_indices,
                const int*   __restrict__ ufi,          // [100000, 50]
                const float* __restrict__ emb_user,     // [100001, 64]
                const float* __restrict__ emb_item,     // [100000, 64]
                const float* __restrict__ affine_w,     // [64]
                const float* __restrict__ affine_b,     // scalar
                float*       __restrict__ rating_out,   // [B]
                float*       __restrict__ gidx_out,     // [B, 50] or null
                int B)
{
    const int warp = (int)((blockIdx.x * blockDim.x + threadIdx.x) >> 5);
    const int lane = threadIdx.x & 31;
    if (warp >= B) return;

    const int   u    = user_indices[warp];
    const int   it   = item_indices[warp];
    const float bias = *affine_b;

    // per-lane: dims [2*lane, 2*lane+1] of item_emb * affine_w
    float2 iw;
    {
        float2 ie = ((const float2*)(emb_item + (size_t)it * D))[lane];
        float2 w  = ((const float2*)affine_w)[lane];
        iw.x = ie.x * w.x;
        iw.y = ie.y * w.y;
    }

    const int* friends = ufi + (size_t)u * CLIP;

    float2 acc  = make_float2(0.f, 0.f);
    int    nfr  = 0;
    float  g_lo = 0.f, g_hi = 0.f;   // gates for friends (lane) and (lane+32)

    #pragma unroll 10
    for (int c = 0; c < CLIP; ++c) {
        const int fid = friends[c];                       // uniform broadcast load
        // padding row (fid==100000) is all-zero in emb_user -> mask mult unneeded
        const float2 f = ((const float2*)(emb_user + (size_t)fid * D))[lane];

        float pd = f.x * iw.x + f.y * iw.y;
        #pragma unroll
        for (int o = 16; o > 0; o >>= 1)
            pd += __shfl_xor_sync(0xffffffffu, pd, o);

        const float gate = 1.f / (1.f + __expf(-(pd + bias)));

        acc.x += f.x * gate;
        acc.y += f.y * gate;
        nfr   += (fid != NF);

        // stash gate in registers for a coalesced write at the end
        if (c == lane)      g_lo = gate;
        if (c == lane + 32) g_hi = gate;
    }

    if (gidx_out) {
        float* gp = gidx_out + (size_t)warp * CLIP;
        gp[lane] = g_lo;                       // friends 0..31
        if (lane < CLIP - 32) gp[lane + 32] = g_hi;  // friends 32..49
    }

    float dot = acc.x * iw.x + acc.y * iw.y;
    #pragma unroll
    for (int o = 16; o > 0; o >>= 1)
        dot += __shfl_xor_sync(0xffffffffu, dot, o);

    if (lane == 0) {
        const float logit = dot / (float)nfr + bias;   // friend_num==0 -> inf/nan, matches ref
        rating_out[warp] = 1.f / (1.f + __expf(-logit));
    }
}

extern "C" void kernel_launch(void* const* d_in, const int* in_sizes, int n_in,
                              void* d_out, int out_size)
{
    const int*   user_indices = (const int*)  d_in[0];
    const int*   item_indices = (const int*)  d_in[1];
    const int*   ufi          = (const int*)  d_in[2];
    const float* emb_user     = (const float*)d_in[3];
    const float* emb_item     = (const float*)d_in[4];
    const float* affine_w     = (const float*)d_in[5];
    const float* affine_b     = (const float*)d_in[6];

    const int B = in_sizes[0];
    float* out = (float*)d_out;

    // outputs: rating [B] then group_idx [B*CLIP] (reference tuple order)
    float* rating = out;
    float* gidx   = (out_size >= B * (1 + CLIP)) ? (out + B) : nullptr;

    const int threads = 256;                 // 8 warps/block, 1 warp per batch row
    const int blocks  = (B * 32 + threads - 1) / threads;
    gmf_kernel<<<blocks, threads>>>(user_indices, item_indices, ufi,
                                    emb_user, emb_item, affine_w, affine_b,
                                    rating, gidx, B);
}

// round 2
// speedup vs baseline: 1.9106x; 1.9106x over previous
#include <cuda_runtime.h>
#include <cuda_bf16.h>

#define NF   100000
#define CLIP 50
#define D    64

// 8 lanes per friend, 4 friends per warp-iteration, 13 iterations (52 slots, 2 padded).
__global__ __launch_bounds__(256, 5)
void gmf_kernel(const int*   __restrict__ user_indices,
                const int*   __restrict__ item_indices,
                const int*   __restrict__ ufi,          // [100000, 50]
                const float* __restrict__ emb_user,     // [100001, 64] (row NF == 0)
                const float* __restrict__ emb_item,     // [100000, 64]
                const float* __restrict__ affine_w,     // [64]
                const float* __restrict__ affine_b,     // scalar
                float*       __restrict__ rating_out,   // [B]
                float*       __restrict__ gidx_out,     // [B, 50] or null
                int B)
{
    const int warp = (int)((blockIdx.x * blockDim.x + threadIdx.x) >> 5);
    const int lane = threadIdx.x & 31;
    if (warp >= B) return;

    const int lig = lane & 7;    // lane in 8-lane group
    const int grp = lane >> 3;   // friend-group 0..3

    const int   u    = user_indices[warp];
    const int   it   = item_indices[warp];
    const float bias = *affine_b;

    // lane holds dims [4*lig, 4*lig+4) and [32+4*lig, 32+4*lig+4) of item*w
    float4 iw_lo, iw_hi;
    {
        const float4* ie = (const float4*)(emb_item + (size_t)it * D);
        const float4* w  = (const float4*)affine_w;
        float4 a = ie[lig],     b0 = w[lig];
        float4 c = ie[lig + 8], d0 = w[lig + 8];
        iw_lo = make_float4(a.x*b0.x, a.y*b0.y, a.z*b0.z, a.w*b0.w);
        iw_hi = make_float4(c.x*d0.x, c.y*d0.y, c.z*d0.z, c.w*d0.w);
    }

    const int* friends = ufi + (size_t)u * CLIP;

    float4 acc_lo = make_float4(0.f, 0.f, 0.f, 0.f);
    float4 acc_hi = make_float4(0.f, 0.f, 0.f, 0.f);
    int    nfr    = 0;                 // uniform within group
    float  ga = 0.f, gb = 0.f;         // gate stash: t==lig, t==lig+8

    #pragma unroll
    for (int t = 0; t < 13; ++t) {
        const int c   = 4 * t + grp;               // friend slot 0..51
        const int fid = (c < CLIP) ? friends[c] : NF;

        const float4* fr = (const float4*)(emb_user + (size_t)fid * D);
        const float4 f_lo = fr[lig];
        const float4 f_hi = fr[lig + 8];

        float pd = f_lo.x*iw_lo.x + f_lo.y*iw_lo.y + f_lo.z*iw_lo.z + f_lo.w*iw_lo.w
                 + f_hi.x*iw_hi.x + f_hi.y*iw_hi.y + f_hi.z*iw_hi.z + f_hi.w*iw_hi.w;
        pd += __shfl_xor_sync(0xffffffffu, pd, 4);
        pd += __shfl_xor_sync(0xffffffffu, pd, 2);
        pd += __shfl_xor_sync(0xffffffffu, pd, 1);

        const float gate = 1.f / (1.f + __expf(-(pd + bias)));

        acc_lo.x += f_lo.x * gate;  acc_lo.y += f_lo.y * gate;
        acc_lo.z += f_lo.z * gate;  acc_lo.w += f_lo.w * gate;
        acc_hi.x += f_hi.x * gate;  acc_hi.y += f_hi.y * gate;
        acc_hi.z += f_hi.z * gate;  acc_hi.w += f_hi.w * gate;

        nfr += (fid != NF);

        if (t == lig)     ga = gate;   // covers t=0..7
        if (t == lig + 8) gb = gate;   // covers t=8..12
    }

    // ---- gate output: gp[4*t + grp] ----
    if (gidx_out) {
        float* gp = gidx_out + (size_t)warp * CLIP;
        gp[4 * lig + grp] = ga;                          // slots 0..31
        const int c2 = 32 + 4 * lig + grp;               // slots 32..49 (+2 padded)
        if (c2 < CLIP) gp[c2] = gb;
    }

    // ---- final: dot(acc, iw) summed over all lanes (dims partitioned per-group,
    //      friends partitioned across groups -> plain 32-lane sum works) ----
    float dot = acc_lo.x*iw_lo.x + acc_lo.y*iw_lo.y + acc_lo.z*iw_lo.z + acc_lo.w*iw_lo.w
              + acc_hi.x*iw_hi.x + acc_hi.y*iw_hi.y + acc_hi.z*iw_hi.z + acc_hi.w*iw_hi.w;
    #pragma unroll
    for (int o = 16; o > 0; o >>= 1)
        dot += __shfl_xor_sync(0xffffffffu, dot, o);

    // friend count: uniform in each group -> sum the 4 groups
    nfr += __shfl_xor_sync(0xffffffffu, nfr, 8);
    nfr += __shfl_xor_sync(0xffffffffu, nfr, 16);

    if (lane == 0) {
        const float logit = dot / (float)nfr + bias;
        rating_out[warp] = 1.f / (1.f + __expf(-logit));
    }
}

extern "C" void kernel_launch(void* const* d_in, const int* in_sizes, int n_in,
                              void* d_out, int out_size)
{
    const int*   user_indices = (const int*)  d_in[0];
    const int*   item_indices = (const int*)  d_in[1];
    const int*   ufi          = (const int*)  d_in[2];
    const float* emb_user     = (const float*)d_in[3];
    const float* emb_item     = (const float*)d_in[4];
    const float* affine_w     = (const float*)d_in[5];
    const float* affine_b     = (const float*)d_in[6];

    const int B = in_sizes[0];
    float* out = (float*)d_out;

    float* rating = out;
    float* gidx   = (out_size >= B * (1 + CLIP)) ? (out + B) : nullptr;

    const int threads = 256;                 // 8 warps/block, 1 warp per batch row
    const int blocks  = (B * 32 + threads - 1) / threads;
    gmf_kernel<<<blocks, threads>>>(user_indices, item_indices, ufi,
                                    emb_user, emb_item, affine_w, affine_b,
                                    rating, gidx, B);
}